// round 1
// baseline (speedup 1.0000x reference)
#include <cuda_runtime.h>
#include <cuda_bf16.h>
#include <math.h>

// Problem dims
#define S_ 256
#define B_ 256
#define H_ 1024
#define L_ 3
#define SB_ (S_ * B_)

// Scratch (no cudaMalloc allowed): layer-0 input-GEMM precompute + double-buffered hidden state
__device__ float g_P0[(size_t)SB_ * H_];          // 256 MB: x @ W_ih0^T + b_ih0 for all (t,b)
__device__ float g_h[2 * L_ * B_ * H_];           // 6 MB: h state, ping-pong over t parity

// ---------------------------------------------------------------------------
// Precompute kernel: P0[m, n] = sum_k x[m,k] * Wih0[n,k] + bih0[n]
// M = 65536, N = 1024, K = 1024.  Tile 64x64, BK=16, 256 threads, 4x4/thread.
// ---------------------------------------------------------------------------
__global__ __launch_bounds__(256) void precompute_p0(
    const float* __restrict__ x, const float* __restrict__ W0,
    const float* __restrict__ b0, float* __restrict__ P0)
{
    __shared__ float As[16][68];
    __shared__ float Ws[16][68];

    const int tid = threadIdx.x;
    const int tx = tid & 15;        // n-dim, 4 cols each
    const int ty = tid >> 4;        // m-dim, 4 rows each
    const int m0 = blockIdx.x * 64;
    const int n0 = blockIdx.y * 64;

    float acc[4][4] = {};

    const int lk = tid & 15;        // k index for loads
    const int lr = tid >> 4;        // row index for loads (0..15)

    for (int k0 = 0; k0 < H_; k0 += 16) {
#pragma unroll
        for (int p = 0; p < 4; ++p)
            As[lk][lr + 16 * p] = x[(size_t)(m0 + lr + 16 * p) * H_ + k0 + lk];
#pragma unroll
        for (int p = 0; p < 4; ++p)
            Ws[lk][lr + 16 * p] = W0[(size_t)(n0 + lr + 16 * p) * H_ + k0 + lk];
        __syncthreads();

#pragma unroll
        for (int kk = 0; kk < 16; ++kk) {
            float4 a = *(const float4*)&As[kk][4 * ty];
            float4 w = *(const float4*)&Ws[kk][4 * tx];
            acc[0][0] += a.x * w.x; acc[0][1] += a.x * w.y; acc[0][2] += a.x * w.z; acc[0][3] += a.x * w.w;
            acc[1][0] += a.y * w.x; acc[1][1] += a.y * w.y; acc[1][2] += a.y * w.z; acc[1][3] += a.y * w.w;
            acc[2][0] += a.z * w.x; acc[2][1] += a.z * w.y; acc[2][2] += a.z * w.z; acc[2][3] += a.z * w.w;
            acc[3][0] += a.w * w.x; acc[3][1] += a.w * w.y; acc[3][2] += a.w * w.z; acc[3][3] += a.w * w.w;
        }
        __syncthreads();
    }

    const int col = n0 + 4 * tx;
    const float4 bv = *(const float4*)&b0[col];
#pragma unroll
    for (int i = 0; i < 4; ++i) {
        const int row = m0 + 4 * ty + i;
        float4 v;
        v.x = acc[i][0] + bv.x;
        v.y = acc[i][1] + bv.y;
        v.z = acc[i][2] + bv.z;
        v.w = acc[i][3] + bv.w;
        *(float4*)&P0[(size_t)row * H_ + col] = v;
    }
}

// ---------------------------------------------------------------------------
// Fused RNN cell: out[b,n] = tanh( [A0@W0^T] + A1@W1^T + base + b1 + b2 )
//   A0/W0 segment optional (null for layer 0, whose input GEMM is in base=P0).
//   M = 256 (batch), N = 1024, K = 1024 per segment.
//   Tile 32x64, BK=32, 256 threads, 2x4/thread -> grid 8x16 = 128 CTAs.
// ---------------------------------------------------------------------------
__global__ __launch_bounds__(256) void rnn_cell(
    const float* __restrict__ A0, const float* __restrict__ W0,
    const float* __restrict__ A1, const float* __restrict__ W1,
    const float* __restrict__ base,
    const float* __restrict__ b1, const float* __restrict__ b2,
    float* __restrict__ hout, float* __restrict__ yout, float* __restrict__ hNout)
{
    __shared__ float As[32][34];
    __shared__ float Ws[32][68];

    const int tid = threadIdx.x;
    const int tx = tid & 15;        // 4 cols each
    const int ty = tid >> 4;        // 2 rows each
    const int m0 = blockIdx.x * 32;
    const int n0 = blockIdx.y * 64;

    float acc[2][4] = {};

    const int lk = tid & 31;
    const int lr = tid >> 5;        // 0..7

#pragma unroll 1
    for (int seg = 0; seg < 2; ++seg) {
        const float* A = seg ? A1 : A0;
        const float* W = seg ? W1 : W0;
        if (A == nullptr) continue;

#pragma unroll 1
        for (int k0 = 0; k0 < H_; k0 += 32) {
#pragma unroll
            for (int p = 0; p < 4; ++p)
                As[lk][lr + 8 * p] = A[(size_t)(m0 + lr + 8 * p) * H_ + k0 + lk];
#pragma unroll
            for (int p = 0; p < 8; ++p)
                Ws[lk][lr + 8 * p] = W[(size_t)(n0 + lr + 8 * p) * H_ + k0 + lk];
            __syncthreads();

#pragma unroll
            for (int kk = 0; kk < 32; ++kk) {
                float2 a = *(const float2*)&As[kk][2 * ty];
                float4 w = *(const float4*)&Ws[kk][4 * tx];
                acc[0][0] += a.x * w.x; acc[0][1] += a.x * w.y;
                acc[0][2] += a.x * w.z; acc[0][3] += a.x * w.w;
                acc[1][0] += a.y * w.x; acc[1][1] += a.y * w.y;
                acc[1][2] += a.y * w.z; acc[1][3] += a.y * w.w;
            }
            __syncthreads();
        }
    }

    const int col = n0 + 4 * tx;
    float4 bias = make_float4(0.f, 0.f, 0.f, 0.f);
    if (b1) {
        float4 t = *(const float4*)&b1[col];
        bias.x += t.x; bias.y += t.y; bias.z += t.z; bias.w += t.w;
    }
    if (b2) {
        float4 t = *(const float4*)&b2[col];
        bias.x += t.x; bias.y += t.y; bias.z += t.z; bias.w += t.w;
    }

#pragma unroll
    for (int i = 0; i < 2; ++i) {
        const int row = m0 + 2 * ty + i;
        const size_t off = (size_t)row * H_ + col;
        float4 pre = bias;
        if (base) {
            float4 t = *(const float4*)&base[off];
            pre.x += t.x; pre.y += t.y; pre.z += t.z; pre.w += t.w;
        }
        float4 v;
        v.x = tanhf(acc[i][0] + pre.x);
        v.y = tanhf(acc[i][1] + pre.y);
        v.z = tanhf(acc[i][2] + pre.z);
        v.w = tanhf(acc[i][3] + pre.w);
        *(float4*)&hout[off] = v;
        if (yout)  *(float4*)&yout[off]  = v;
        if (hNout) *(float4*)&hNout[off] = v;
    }
}

// ---------------------------------------------------------------------------
extern "C" void kernel_launch(void* const* d_in, const int* in_sizes, int n_in,
                              void* d_out, int out_size)
{
    const float* x    = (const float*)d_in[0];   // [S, B, H]
    const float* h0   = (const float*)d_in[1];   // [L, B, H]
    const float* Wih  = (const float*)d_in[2];   // [L, H, H]
    const float* Whh  = (const float*)d_in[3];   // [L, H, H]
    const float* bih  = (const float*)d_in[4];   // [L, H]
    const float* bhh  = (const float*)d_in[5];   // [L, H]
    float* out = (float*)d_out;

    float *P0, *hbuf;
    cudaGetSymbolAddress((void**)&P0,   g_P0);
    cudaGetSymbolAddress((void**)&hbuf, g_h);

    const size_t LBH = (size_t)L_ * B_ * H_;
    const size_t ySize = (size_t)SB_ * H_;

    // h state ping-pong: hb(buf, l)
    auto hb = [&](int buf, int l) { return hbuf + ((size_t)buf * L_ + l) * B_ * H_; };

    // initial hidden state
    cudaMemcpyAsync(hbuf, h0, LBH * sizeof(float), cudaMemcpyDeviceToDevice);

    // precompute layer-0 input GEMM for all timesteps
    {
        dim3 grid(SB_ / 64, H_ / 64);
        precompute_p0<<<grid, 256>>>(x, Wih, bih, P0);
    }

    float* y  = out;
    float* hN = ((size_t)out_size >= ySize + LBH) ? (out + ySize) : nullptr;

    const dim3 cgrid(B_ / 32, H_ / 64);

    for (int t = 0; t < S_; ++t) {
        const int pb = t & 1;         // read buffer
        const int cb = 1 - pb;        // write buffer
        for (int l = 0; l < L_; ++l) {
            const float* A0   = (l == 0) ? nullptr : hb(cb, l - 1);  // this-step output of layer l-1
            const float* W0   = (l == 0) ? nullptr : (Wih + (size_t)l * H_ * H_);
            const float* A1   = hb(pb, l);                            // h_prev of this layer
            const float* W1   = Whh + (size_t)l * H_ * H_;
            const float* base = (l == 0) ? (P0 + (size_t)t * B_ * H_) : nullptr;
            const float* b1p  = (l == 0) ? nullptr : (bih + (size_t)l * H_);  // bih0 folded into P0
            const float* b2p  = bhh + (size_t)l * H_;
            float* ho   = hb(cb, l);
            float* yo   = (l == L_ - 1) ? (y + (size_t)t * B_ * H_) : nullptr;
            float* hNo  = (t == S_ - 1 && hN) ? (hN + (size_t)l * B_ * H_) : nullptr;

            rnn_cell<<<cgrid, 256>>>(A0, W0, A1, W1, base, b1p, b2p, ho, yo, hNo);
        }
    }
}

// round 2
// speedup vs baseline: 1.0071x; 1.0071x over previous
#include <cuda_runtime.h>
#include <cuda_bf16.h>
#include <math.h>

// Problem dims
#define S_ 256
#define B_ 256
#define H_ 1024
#define L_ 3
#define SB_ (S_ * B_)

// Scratch (no cudaMalloc allowed): layer-0 input-GEMM precompute + double-buffered hidden state
__device__ float g_P0[(size_t)SB_ * H_];          // 256 MB: x @ W_ih0^T + b_ih0 for all (t,b)
__device__ float g_h[2 * L_ * B_ * H_];           // 6 MB: h state, ping-pong over t parity

// ---------------------------------------------------------------------------
// Precompute kernel: P0[m, n] = sum_k x[m,k] * Wih0[n,k] + bih0[n]
// M = 65536, N = 1024, K = 1024.  Tile 64x64, BK=16, 256 threads, 4x4/thread.
// ---------------------------------------------------------------------------
__global__ __launch_bounds__(256) void precompute_p0(
    const float* __restrict__ x, const float* __restrict__ W0,
    const float* __restrict__ b0, float* __restrict__ P0)
{
    __shared__ float As[16][68];
    __shared__ float Ws[16][68];

    const int tid = threadIdx.x;
    const int tx = tid & 15;        // n-dim, 4 cols each
    const int ty = tid >> 4;        // m-dim, 4 rows each
    const int m0 = blockIdx.x * 64;
    const int n0 = blockIdx.y * 64;

    float acc[4][4] = {};

    const int lk = tid & 15;        // k index for loads
    const int lr = tid >> 4;        // row index for loads (0..15)

    for (int k0 = 0; k0 < H_; k0 += 16) {
#pragma unroll
        for (int p = 0; p < 4; ++p)
            As[lk][lr + 16 * p] = x[(size_t)(m0 + lr + 16 * p) * H_ + k0 + lk];
#pragma unroll
        for (int p = 0; p < 4; ++p)
            Ws[lk][lr + 16 * p] = W0[(size_t)(n0 + lr + 16 * p) * H_ + k0 + lk];
        __syncthreads();

#pragma unroll
        for (int kk = 0; kk < 16; ++kk) {
            float4 a = *(const float4*)&As[kk][4 * ty];
            float4 w = *(const float4*)&Ws[kk][4 * tx];
            acc[0][0] += a.x * w.x; acc[0][1] += a.x * w.y; acc[0][2] += a.x * w.z; acc[0][3] += a.x * w.w;
            acc[1][0] += a.y * w.x; acc[1][1] += a.y * w.y; acc[1][2] += a.y * w.z; acc[1][3] += a.y * w.w;
            acc[2][0] += a.z * w.x; acc[2][1] += a.z * w.y; acc[2][2] += a.z * w.z; acc[2][3] += a.z * w.w;
            acc[3][0] += a.w * w.x; acc[3][1] += a.w * w.y; acc[3][2] += a.w * w.z; acc[3][3] += a.w * w.w;
        }
        __syncthreads();
    }

    const int col = n0 + 4 * tx;
    const float4 bv = *(const float4*)&b0[col];
#pragma unroll
    for (int i = 0; i < 4; ++i) {
        const int row = m0 + 4 * ty + i;
        float4 v;
        v.x = acc[i][0] + bv.x;
        v.y = acc[i][1] + bv.y;
        v.z = acc[i][2] + bv.z;
        v.w = acc[i][3] + bv.w;
        *(float4*)&P0[(size_t)row * H_ + col] = v;
    }
}

// ---------------------------------------------------------------------------
// Fused RNN cell: out[b,n] = tanh( [A0@W0^T] + A1@W1^T + base + b1 + b2 )
//   A0/W0 segment optional (null for layer 0, whose input GEMM is in base=P0).
//   M = 256 (batch), N = 1024, K = 1024 per segment.
//   Tile 32x64, BK=32, 256 threads, 2x4/thread -> grid 8x16 = 128 CTAs.
// ---------------------------------------------------------------------------
__global__ __launch_bounds__(256) void rnn_cell(
    const float* __restrict__ A0, const float* __restrict__ W0,
    const float* __restrict__ A1, const float* __restrict__ W1,
    const float* __restrict__ base,
    const float* __restrict__ b1, const float* __restrict__ b2,
    float* __restrict__ hout, float* __restrict__ yout, float* __restrict__ hNout)
{
    __shared__ float As[32][34];
    __shared__ float Ws[32][68];

    const int tid = threadIdx.x;
    const int tx = tid & 15;        // 4 cols each
    const int ty = tid >> 4;        // 2 rows each
    const int m0 = blockIdx.x * 32;
    const int n0 = blockIdx.y * 64;

    float acc[2][4] = {};

    const int lk = tid & 31;
    const int lr = tid >> 5;        // 0..7

#pragma unroll 1
    for (int seg = 0; seg < 2; ++seg) {
        const float* A = seg ? A1 : A0;
        const float* W = seg ? W1 : W0;
        if (A == nullptr) continue;

#pragma unroll 1
        for (int k0 = 0; k0 < H_; k0 += 32) {
#pragma unroll
            for (int p = 0; p < 4; ++p)
                As[lk][lr + 8 * p] = A[(size_t)(m0 + lr + 8 * p) * H_ + k0 + lk];
#pragma unroll
            for (int p = 0; p < 8; ++p)
                Ws[lk][lr + 8 * p] = W[(size_t)(n0 + lr + 8 * p) * H_ + k0 + lk];
            __syncthreads();

#pragma unroll
            for (int kk = 0; kk < 32; ++kk) {
                float2 a = *(const float2*)&As[kk][2 * ty];
                float4 w = *(const float4*)&Ws[kk][4 * tx];
                acc[0][0] += a.x * w.x; acc[0][1] += a.x * w.y;
                acc[0][2] += a.x * w.z; acc[0][3] += a.x * w.w;
                acc[1][0] += a.y * w.x; acc[1][1] += a.y * w.y;
                acc[1][2] += a.y * w.z; acc[1][3] += a.y * w.w;
            }
            __syncthreads();
        }
    }

    const int col = n0 + 4 * tx;
    float4 bias = make_float4(0.f, 0.f, 0.f, 0.f);
    if (b1) {
        float4 t = *(const float4*)&b1[col];
        bias.x += t.x; bias.y += t.y; bias.z += t.z; bias.w += t.w;
    }
    if (b2) {
        float4 t = *(const float4*)&b2[col];
        bias.x += t.x; bias.y += t.y; bias.z += t.z; bias.w += t.w;
    }

#pragma unroll
    for (int i = 0; i < 2; ++i) {
        const int row = m0 + 2 * ty + i;
        const size_t off = (size_t)row * H_ + col;
        float4 pre = bias;
        if (base) {
            float4 t = *(const float4*)&base[off];
            pre.x += t.x; pre.y += t.y; pre.z += t.z; pre.w += t.w;
        }
        float4 v;
        v.x = tanhf(acc[i][0] + pre.x);
        v.y = tanhf(acc[i][1] + pre.y);
        v.z = tanhf(acc[i][2] + pre.z);
        v.w = tanhf(acc[i][3] + pre.w);
        *(float4*)&hout[off] = v;
        if (yout)  *(float4*)&yout[off]  = v;
        if (hNout) *(float4*)&hNout[off] = v;
    }
}

// ---------------------------------------------------------------------------
extern "C" void kernel_launch(void* const* d_in, const int* in_sizes, int n_in,
                              void* d_out, int out_size)
{
    const float* x    = (const float*)d_in[0];   // [S, B, H]
    const float* h0   = (const float*)d_in[1];   // [L, B, H]
    const float* Wih  = (const float*)d_in[2];   // [L, H, H]
    const float* Whh  = (const float*)d_in[3];   // [L, H, H]
    const float* bih  = (const float*)d_in[4];   // [L, H]
    const float* bhh  = (const float*)d_in[5];   // [L, H]
    float* out = (float*)d_out;

    float *P0, *hbuf;
    cudaGetSymbolAddress((void**)&P0,   g_P0);
    cudaGetSymbolAddress((void**)&hbuf, g_h);

    const size_t LBH = (size_t)L_ * B_ * H_;
    const size_t ySize = (size_t)SB_ * H_;

    // h state ping-pong: hb(buf, l)
    auto hb = [&](int buf, int l) { return hbuf + ((size_t)buf * L_ + l) * B_ * H_; };

    // initial hidden state
    cudaMemcpyAsync(hbuf, h0, LBH * sizeof(float), cudaMemcpyDeviceToDevice);

    // precompute layer-0 input GEMM for all timesteps
    {
        dim3 grid(SB_ / 64, H_ / 64);
        precompute_p0<<<grid, 256>>>(x, Wih, bih, P0);
    }

    float* y  = out;
    float* hN = ((size_t)out_size >= ySize + LBH) ? (out + ySize) : nullptr;

    const dim3 cgrid(B_ / 32, H_ / 64);

    for (int t = 0; t < S_; ++t) {
        const int pb = t & 1;         // read buffer
        const int cb = 1 - pb;        // write buffer
        for (int l = 0; l < L_; ++l) {
            const float* A0   = (l == 0) ? nullptr : hb(cb, l - 1);  // this-step output of layer l-1
            const float* W0   = (l == 0) ? nullptr : (Wih + (size_t)l * H_ * H_);
            const float* A1   = hb(pb, l);                            // h_prev of this layer
            const float* W1   = Whh + (size_t)l * H_ * H_;
            const float* base = (l == 0) ? (P0 + (size_t)t * B_ * H_) : nullptr;
            const float* b1p  = (l == 0) ? nullptr : (bih + (size_t)l * H_);  // bih0 folded into P0
            const float* b2p  = bhh + (size_t)l * H_;
            float* ho   = hb(cb, l);
            float* yo   = (l == L_ - 1) ? (y + (size_t)t * B_ * H_) : nullptr;
            float* hNo  = (t == S_ - 1 && hN) ? (hN + (size_t)l * B_ * H_) : nullptr;

            rnn_cell<<<cgrid, 256>>>(A0, W0, A1, W1, base, b1p, b2p, ho, yo, hNo);
        }
    }
}

// round 4
// speedup vs baseline: 3.1452x; 3.1229x over previous
#include <cuda_runtime.h>
#include <cuda_bf16.h>
#include <math.h>
#include <stdint.h>

#define S_ 256
#define B_ 256
#define H_ 1024
#define L_ 3
#define SB_ (S_ * B_)
#define BH_ (B_ * H_)
#define HH_ (H_ * H_)

// ---------------- scratch (__device__ globals; no cudaMalloc) ----------------
__device__ __align__(1024) float         g_P0[(size_t)SB_ * H_];
__device__ __align__(1024) __nv_bfloat16 g_xhi[(size_t)SB_ * H_];
__device__ __align__(1024) __nv_bfloat16 g_xlo[(size_t)SB_ * H_];
__device__ __align__(1024) __nv_bfloat16 g_WihHi[(size_t)L_ * HH_];
__device__ __align__(1024) __nv_bfloat16 g_WihLo[(size_t)L_ * HH_];
__device__ __align__(1024) __nv_bfloat16 g_WhhHi[(size_t)L_ * HH_];
__device__ __align__(1024) __nv_bfloat16 g_WhhLo[(size_t)L_ * HH_];
__device__ __align__(1024) __nv_bfloat16 g_hHi[2 * L_ * BH_];
__device__ __align__(1024) __nv_bfloat16 g_hLo[2 * L_ * BH_];

// ---------------- helpers ----------------
__device__ __forceinline__ uint32_t smem_to_u32(const void* p) {
    uint32_t a;
    asm("{ .reg .u64 t; cvta.to.shared.u64 t, %1; cvt.u32.u64 %0, t; }" : "=r"(a) : "l"(p));
    return a;
}
__device__ __forceinline__ void cp16(uint32_t dst, const void* src) {
    asm volatile("cp.async.cg.shared.global [%0], [%1], 16;" :: "r"(dst), "l"(src) : "memory");
}
#define CP_COMMIT() asm volatile("cp.async.commit_group;" ::: "memory")
template <int N> __device__ __forceinline__ void cp_wait() {
    asm volatile("cp.async.wait_group %0;" :: "n"(N) : "memory");
}
__device__ __forceinline__ void ldsm4(uint32_t& r0, uint32_t& r1, uint32_t& r2, uint32_t& r3,
                                      uint32_t addr) {
    asm volatile("ldmatrix.sync.aligned.m8n8.x4.shared.b16 {%0,%1,%2,%3}, [%4];"
                 : "=r"(r0), "=r"(r1), "=r"(r2), "=r"(r3) : "r"(addr));
}
__device__ __forceinline__ void mma16816(float* d, const uint32_t* a, uint32_t b0, uint32_t b1) {
    asm volatile(
        "mma.sync.aligned.m16n8k16.row.col.f32.bf16.bf16.f32 "
        "{%0,%1,%2,%3}, {%4,%5,%6,%7}, {%8,%9}, {%0,%1,%2,%3};"
        : "+f"(d[0]), "+f"(d[1]), "+f"(d[2]), "+f"(d[3])
        : "r"(a[0]), "r"(a[1]), "r"(a[2]), "r"(a[3]), "r"(b0), "r"(b1));
}

// swizzled in-stage byte offset: row has 64 bf16 = 128B; chunk = 16B unit
__device__ __forceinline__ uint32_t swz(int row, int chunk) {
    return (uint32_t)(row * 128 + ((chunk ^ (row & 7)) << 4));
}

// ---------------- GEMM kernel (HMMA bf16, SS via smem) ----------------
// D[m,n] = sum_g A[g][m,:] . B[g][n,:]  (K=1024/seg; all rows stride H_)
// out = (tanh?)(D + base + bias1 + bias2)
struct GArgs {
    const __nv_bfloat16* A[6];
    const __nv_bfloat16* B[6];
    const float* base;
    const float* bias1;
    const float* bias2;
    float* outf;
    float* outf2;
    __nv_bfloat16* ohi;
    __nv_bfloat16* olo;
    int nseg;
    int dotanh;
};
struct DiagArgs { GArgs c[3]; };

#define MT 64
#define NT 128
#define KS 64                       // K per stage
#define STAGE_A 8192                // 64 x 64 bf16
#define STAGE_B 16384               // 128 x 64 bf16
#define STAGE_BYTES (STAGE_A + STAGE_B)   // 24576
#define NSTAGE 3
#define SMEM_DYN (NSTAGE * STAGE_BYTES + 1024)

__global__ __launch_bounds__(128, 2) void gemm_diag(DiagArgs da)
{
    extern __shared__ char smraw[];
    const uint32_t smem = (smem_to_u32(smraw) + 1023u) & ~1023u;

    const GArgs g = da.c[blockIdx.z];
    const int tid  = threadIdx.x;
    const int warp = tid >> 5;
    const int lane = tid & 31;
    const int wm = (warp & 1) * 32;       // warp m offset in tile
    const int wn = (warp >> 1) * 64;      // warp n offset in tile
    const int m0 = blockIdx.y * MT;
    const int n0 = blockIdx.x * NT;
    const int total = g.nseg * (1024 / KS);

    float acc[2][8][4];
#pragma unroll
    for (int i = 0; i < 2; ++i)
#pragma unroll
        for (int j = 0; j < 8; ++j)
#pragma unroll
            for (int k = 0; k < 4; ++k) acc[i][j][k] = 0.f;

    // ---- stage loader: A 4 chunks + B 8 chunks per thread ----
    auto load_stage = [&](int s) {
        const int sg = s >> 4;
        const int k0 = (s & 15) * KS;
        const uint32_t sa = smem + (s % NSTAGE) * STAGE_BYTES;
        const uint32_t sb = sa + STAGE_A;
        const __nv_bfloat16* Ag = g.A[sg];
        const __nv_bfloat16* Bg = g.B[sg];
#pragma unroll
        for (int i = 0; i < 4; ++i) {
            const int idx = tid + 128 * i;        // 0..511
            const int row = idx >> 3;             // 0..63
            const int c   = idx & 7;
            cp16(sa + swz(row, c), Ag + (size_t)(m0 + row) * H_ + k0 + c * 8);
        }
#pragma unroll
        for (int i = 0; i < 8; ++i) {
            const int idx = tid + 128 * i;        // 0..1023
            const int row = idx >> 3;             // 0..127
            const int c   = idx & 7;
            cp16(sb + swz(row, c), Bg + (size_t)(n0 + row) * H_ + k0 + c * 8);
        }
        CP_COMMIT();
    };

    load_stage(0);
    load_stage(1);

#pragma unroll 1
    for (int s = 0; s < total; ++s) {
        if (s + 2 < total) cp_wait<1>(); else cp_wait<0>();
        __syncthreads();
        if (s + 2 < total) load_stage(s + 2);

        const uint32_t sa = smem + (s % NSTAGE) * STAGE_BYTES;
        const uint32_t sb = sa + STAGE_A;

#pragma unroll
        for (int kk = 0; kk < 4; ++kk) {
            // A frags: 2 x ldmatrix.x4 (16x16 each)
            uint32_t afr[2][4];
#pragma unroll
            for (int mt = 0; mt < 2; ++mt) {
                const int row = wm + mt * 16 + (lane & 15);
                const int ch  = kk * 2 + (lane >> 4);
                ldsm4(afr[mt][0], afr[mt][1], afr[mt][2], afr[mt][3], sa + swz(row, ch));
            }
            // B frags: 4 x ldmatrix.x4 (each covers two n8 tiles)
            uint32_t bfr[4][4];
#pragma unroll
            for (int nt = 0; nt < 4; ++nt) {
                const int row = wn + nt * 16 + (lane & 7) + ((lane >> 4) << 3);
                const int ch  = kk * 2 + ((lane >> 3) & 1);
                ldsm4(bfr[nt][0], bfr[nt][1], bfr[nt][2], bfr[nt][3], sb + swz(row, ch));
            }
#pragma unroll
            for (int mt = 0; mt < 2; ++mt)
#pragma unroll
                for (int j = 0; j < 8; ++j)
                    mma16816(acc[mt][j], afr[mt], bfr[j >> 1][(j & 1) * 2],
                             bfr[j >> 1][(j & 1) * 2 + 1]);
        }
    }

    // ---- epilogue ----
#pragma unroll
    for (int mt = 0; mt < 2; ++mt) {
#pragma unroll
        for (int h = 0; h < 2; ++h) {
            const int row = m0 + wm + mt * 16 + (lane >> 2) + h * 8;
            const size_t rowoff = (size_t)row * H_;
#pragma unroll
            for (int j = 0; j < 8; ++j) {
                const int col = n0 + wn + j * 8 + (lane & 3) * 2;
                float v0 = acc[mt][j][h * 2 + 0];
                float v1 = acc[mt][j][h * 2 + 1];
                if (g.bias1) { v0 += g.bias1[col]; v1 += g.bias1[col + 1]; }
                if (g.bias2) { v0 += g.bias2[col]; v1 += g.bias2[col + 1]; }
                if (g.base)  { const float2 b = *(const float2*)(g.base + rowoff + col);
                               v0 += b.x; v1 += b.y; }
                if (g.dotanh) { v0 = tanhf(v0); v1 = tanhf(v1); }
                const size_t off = rowoff + col;
                if (g.outf)  *(float2*)(g.outf + off)  = make_float2(v0, v1);
                if (g.outf2) *(float2*)(g.outf2 + off) = make_float2(v0, v1);
                if (g.ohi) {
                    __nv_bfloat16 h0 = __float2bfloat16(v0);
                    __nv_bfloat16 h1 = __float2bfloat16(v1);
                    __nv_bfloat162 hh; hh.x = h0; hh.y = h1;
                    *(__nv_bfloat162*)(g.ohi + off) = hh;
                    __nv_bfloat162 ll;
                    ll.x = __float2bfloat16(v0 - __bfloat162float(h0));
                    ll.y = __float2bfloat16(v1 - __bfloat162float(h1));
                    *(__nv_bfloat162*)(g.olo + off) = ll;
                }
            }
        }
    }
}

// ---------------- fp32 -> bf16 hi/lo split ----------------
__global__ __launch_bounds__(256) void split_f32(const float* __restrict__ in,
                                                 __nv_bfloat16* __restrict__ hi,
                                                 __nv_bfloat16* __restrict__ lo)
{
    const size_t i = ((size_t)blockIdx.x * 256 + threadIdx.x) * 4;
    float4 v = *(const float4*)(in + i);
    __nv_bfloat16 h0 = __float2bfloat16(v.x), h1 = __float2bfloat16(v.y);
    __nv_bfloat16 h2 = __float2bfloat16(v.z), h3 = __float2bfloat16(v.w);
    __nv_bfloat162 hA; hA.x = h0; hA.y = h1;
    __nv_bfloat162 hB; hB.x = h2; hB.y = h3;
    *(__nv_bfloat162*)(hi + i)     = hA;
    *(__nv_bfloat162*)(hi + i + 2) = hB;
    __nv_bfloat162 lA, lB;
    lA.x = __float2bfloat16(v.x - __bfloat162float(h0));
    lA.y = __float2bfloat16(v.y - __bfloat162float(h1));
    lB.x = __float2bfloat16(v.z - __bfloat162float(h2));
    lB.y = __float2bfloat16(v.w - __bfloat162float(h3));
    *(__nv_bfloat162*)(lo + i)     = lA;
    *(__nv_bfloat162*)(lo + i + 2) = lB;
}

// ---------------- host ----------------
extern "C" void kernel_launch(void* const* d_in, const int* in_sizes, int n_in,
                              void* d_out, int out_size)
{
    const float* x   = (const float*)d_in[0];
    const float* h0  = (const float*)d_in[1];
    const float* Wih = (const float*)d_in[2];
    const float* Whh = (const float*)d_in[3];
    const float* bih = (const float*)d_in[4];
    const float* bhh = (const float*)d_in[5];
    float* out = (float*)d_out;

    float *P0;
    __nv_bfloat16 *xhi, *xlo, *WihHi, *WihLo, *WhhHi, *WhhLo, *hHi, *hLo;
    cudaGetSymbolAddress((void**)&P0,    g_P0);
    cudaGetSymbolAddress((void**)&xhi,   g_xhi);
    cudaGetSymbolAddress((void**)&xlo,   g_xlo);
    cudaGetSymbolAddress((void**)&WihHi, g_WihHi);
    cudaGetSymbolAddress((void**)&WihLo, g_WihLo);
    cudaGetSymbolAddress((void**)&WhhHi, g_WhhHi);
    cudaGetSymbolAddress((void**)&WhhLo, g_WhhLo);
    cudaGetSymbolAddress((void**)&hHi,   g_hHi);
    cudaGetSymbolAddress((void**)&hLo,   g_hLo);

    cudaFuncSetAttribute(gemm_diag, cudaFuncAttributeMaxDynamicSharedMemorySize, SMEM_DYN);

    split_f32<<<SB_ * (H_ / 1024), 256>>>(x, xhi, xlo);
    split_f32<<<L_ * (HH_ / 1024), 256>>>(Wih, WihHi, WihLo);
    split_f32<<<L_ * (HH_ / 1024), 256>>>(Whh, WhhHi, WhhLo);
    split_f32<<<L_ * (BH_ / 1024), 256>>>(h0, hHi, hLo);   // -> buf 0

    auto HHI = [&](int buf, int l) { return hHi + ((size_t)buf * L_ + l) * BH_; };
    auto HLO = [&](int buf, int l) { return hLo + ((size_t)buf * L_ + l) * BH_; };

    // P0 = x @ Wih0^T + bih0
    {
        DiagArgs da = {};
        GArgs& a = da.c[0];
        a.A[0] = xhi; a.B[0] = WihHi;
        a.A[1] = xhi; a.B[1] = WihLo;
        a.A[2] = xlo; a.B[2] = WihHi;
        a.nseg = 3;
        a.bias1 = bih;
        a.outf = P0;
        gemm_diag<<<dim3(H_ / NT, SB_ / MT, 1), 128, SMEM_DYN>>>(da);
    }

    const size_t ySize = (size_t)SB_ * H_;
    float* y  = out;
    float* hN = ((size_t)out_size >= ySize + (size_t)L_ * BH_) ? (out + ySize) : nullptr;

    for (int d = 0; d < S_ + L_ - 1; ++d) {
        DiagArgs da = {};
        int nc = 0;
        const int lmin = (d > S_ - 1) ? (d - (S_ - 1)) : 0;
        const int lmax = (d < L_ - 1) ? d : (L_ - 1);
        for (int l = lmin; l <= lmax; ++l) {
            const int t = d - l;
            const int pb = t & 1;
            const int cb = 1 - pb;
            GArgs& a = da.c[nc++];
            int ns = 0;
            if (l > 0) {
                const __nv_bfloat16* inHi = HHI(cb, l - 1);
                const __nv_bfloat16* inLo = HLO(cb, l - 1);
                const __nv_bfloat16* WHi = WihHi + (size_t)l * HH_;
                const __nv_bfloat16* WLo = WihLo + (size_t)l * HH_;
                a.A[ns] = inHi; a.B[ns] = WHi; ++ns;
                a.A[ns] = inHi; a.B[ns] = WLo; ++ns;
                a.A[ns] = inLo; a.B[ns] = WHi; ++ns;
            }
            {
                const __nv_bfloat16* hpHi = HHI(pb, l);
                const __nv_bfloat16* hpLo = HLO(pb, l);
                const __nv_bfloat16* WHi = WhhHi + (size_t)l * HH_;
                const __nv_bfloat16* WLo = WhhLo + (size_t)l * HH_;
                a.A[ns] = hpHi; a.B[ns] = WHi; ++ns;
                a.A[ns] = hpHi; a.B[ns] = WLo; ++ns;
                a.A[ns] = hpLo; a.B[ns] = WHi; ++ns;
            }
            a.nseg = ns;
            a.dotanh = 1;
            if (l == 0) {
                a.base = P0 + (size_t)t * BH_;        // includes bih0
                a.bias1 = bhh;
            } else {
                a.bias1 = bih + (size_t)l * H_;
                a.bias2 = bhh + (size_t)l * H_;
            }
            a.ohi = HHI(cb, l);
            a.olo = HLO(cb, l);
            if (l == L_ - 1) a.outf = y + (size_t)t * BH_;
            if (t == S_ - 1 && hN) {
                if (a.outf) a.outf2 = hN + (size_t)l * BH_;
                else        a.outf  = hN + (size_t)l * BH_;
            }
        }
        gemm_diag<<<dim3(H_ / NT, B_ / MT, nc), 128, SMEM_DYN>>>(da);
    }
}